// round 4
// baseline (speedup 1.0000x reference)
#include <cuda_runtime.h>
#include <cuda_bf16.h>
#include <float.h>
#include <stdint.h>

// ---------------------------------------------------------------------------
// Problem constants
// ---------------------------------------------------------------------------
#define NN   50000      // nodes
#define EE   250000     // raw edges
#define ET   300000     // edges + self loops
#define NG   64         // graphs

// ---------------------------------------------------------------------------
// Device scratch (static; ping-pong buffers to minimize static footprint)
// ---------------------------------------------------------------------------
__device__ __align__(16) float g_P[(size_t)NN * 1024];   // h1 / h2 / h3
__device__ __align__(16) float g_Q[(size_t)NN * 1024];   // o1 / o2 / o3

__device__ float g_als[NN * 8];
__device__ float g_ald[NN * 8];
__device__ float g_emax[NN * 8];
__device__ float g_dinv[NN * 8];

__device__ int   g_srcS[ET];       // src per edge, CSR-sorted by dst
__device__ int   g_deg[NN];
__device__ int   g_off[NN + 1];
__device__ int   g_cur[NN];

__device__ float g_pool[NG * 128];
__device__ int   g_cnt[NG];

// dtype flags: 1 if the corresponding input is int64 (read low words)
__device__ int g_ei64;
__device__ int g_b64;

__device__ __forceinline__ int clampN(int v) {
    return (v < 0) ? 0 : ((v >= NN) ? NN - 1 : v);
}

// ---------------------------------------------------------------------------
// Dtype detection: int64 little-endian values < 2^31 have zero high words.
// ---------------------------------------------------------------------------
__global__ void k_detect(const int* __restrict__ ei, const int* __restrict__ batch) {
    if (threadIdx.x != 0) return;
    int all0 = 1;
    for (int i = 1; i < 1024; i += 2)
        if (ei[i] != 0) { all0 = 0; break; }
    g_ei64 = all0;
    all0 = 1;
    for (int i = NN - 1023; i < NN; i += 2)
        if (batch[i] != 0) { all0 = 0; break; }
    g_b64 = all0;
}

__device__ __forceinline__ int ld_ei(const int* __restrict__ ei, int i) {
    return g_ei64 ? ei[2 * i] : ei[i];
}
__device__ __forceinline__ int ld_b(const int* __restrict__ b, int i) {
    return g_b64 ? b[2 * i] : b[i];
}

// ---------------------------------------------------------------------------
// CSR build
// ---------------------------------------------------------------------------
__global__ void k_zero_deg() {
    int i = blockIdx.x * blockDim.x + threadIdx.x;
    if (i < NN) g_deg[i] = 0;
}

__global__ void k_count(const int* __restrict__ ei) {
    int e = blockIdx.x * blockDim.x + threadIdx.x;
    if (e >= ET) return;
    int dst = (e < EE) ? clampN(ld_ei(ei, EE + e)) : (e - EE);
    atomicAdd(&g_deg[dst], 1);
}

// Strip-based exclusive scan (1 block, 256 threads): simple and verifiable.
__global__ void k_scan_simple() {
    __shared__ int strip[256];
    int tid = threadIdx.x;
    const int SZ = (NN + 255) / 256;
    int lo = tid * SZ; if (lo > NN) lo = NN;
    int hi = lo + SZ;  if (hi > NN) hi = NN;
    int s = 0;
    for (int i = lo; i < hi; i++) s += g_deg[i];
    strip[tid] = s;
    __syncthreads();
    if (tid == 0) {
        int run = 0;
        for (int i = 0; i < 256; i++) { int t = strip[i]; strip[i] = run; run += t; }
        g_off[NN] = run;
    }
    __syncthreads();
    int run = strip[tid];
    for (int i = lo; i < hi; i++) { g_off[i] = run; run += g_deg[i]; }
}

__global__ void k_init_cur() {
    int i = blockIdx.x * blockDim.x + threadIdx.x;
    if (i < NN) g_cur[i] = g_off[i];
}

__global__ void k_scatter(const int* __restrict__ ei) {
    int e = blockIdx.x * blockDim.x + threadIdx.x;
    if (e >= ET) return;
    int src, dst;
    if (e < EE) { src = clampN(ld_ei(ei, e)); dst = clampN(ld_ei(ei, EE + e)); }
    else        { src = e - EE;               dst = e - EE; }
    int pos = atomicAdd(&g_cur[dst], 1);
    if (pos >= 0 && pos < ET) g_srcS[pos] = src;
}

// ---------------------------------------------------------------------------
// Layer-1 GEMM: h1 = x(50000x11) @ W1(11x1024)
// ---------------------------------------------------------------------------
__global__ void k_gemm1(const float* __restrict__ x, const float* __restrict__ W,
                        float* __restrict__ h) {
    __shared__ float xs[11];
    int n = blockIdx.x;
    int col = blockIdx.y * 256 + threadIdx.x;
    if (threadIdx.x < 11) xs[threadIdx.x] = x[n * 11 + threadIdx.x];
    __syncthreads();
    float acc = 0.f;
#pragma unroll
    for (int k = 0; k < 11; k++) acc += xs[k] * W[k * 1024 + col];
    h[(size_t)n * 1024 + col] = acc;
}

// ---------------------------------------------------------------------------
// General SGEMM: C(NrowsxM) = A(NrowsxK) @ B(KxM), 128x128x8, 8x8 / thread
// ---------------------------------------------------------------------------
__global__ __launch_bounds__(256) void k_sgemm(const float* __restrict__ A,
                                               const float* __restrict__ B,
                                               float* __restrict__ C,
                                               int Nrows, int K, int M) {
    __shared__ __align__(16) float As[8][128];
    __shared__ __align__(16) float Bs[8][128];
    int tid = threadIdx.x;
    int rowBase = blockIdx.x * 128;
    int colBase = blockIdx.y * 128;

    int ar = tid >> 1;
    int ak = (tid & 1) * 4;
    int br = tid >> 5;
    int bc = (tid & 31) * 4;
    int ty = tid >> 4, tx = tid & 15;

    bool avalid = (rowBase + ar) < Nrows;
    const float* Aptr = A + (size_t)(rowBase + ar) * K + ak;
    const float* Bptr = B + (size_t)br * M + colBase + bc;

    float acc[8][8];
#pragma unroll
    for (int i = 0; i < 8; i++)
#pragma unroll
        for (int j = 0; j < 8; j++) acc[i][j] = 0.f;

    for (int kt = 0; kt < K; kt += 8) {
        float4 av = avalid ? *(const float4*)(Aptr + kt) : make_float4(0, 0, 0, 0);
        float4 bv = *(const float4*)(Bptr + (size_t)kt * M);
        __syncthreads();
        As[ak + 0][ar] = av.x;
        As[ak + 1][ar] = av.y;
        As[ak + 2][ar] = av.z;
        As[ak + 3][ar] = av.w;
        *(float4*)&Bs[br][bc] = bv;
        __syncthreads();
#pragma unroll
        for (int k = 0; k < 8; k++) {
            float a[8], b[8];
            *(float4*)(a)     = *(const float4*)&As[k][ty * 8];
            *(float4*)(a + 4) = *(const float4*)&As[k][ty * 8 + 4];
            *(float4*)(b)     = *(const float4*)&Bs[k][tx * 8];
            *(float4*)(b + 4) = *(const float4*)&Bs[k][tx * 8 + 4];
#pragma unroll
            for (int i = 0; i < 8; i++)
#pragma unroll
                for (int j = 0; j < 8; j++) acc[i][j] += a[i] * b[j];
        }
    }

#pragma unroll
    for (int i = 0; i < 8; i++) {
        int r = rowBase + ty * 8 + i;
        if (r < Nrows) {
            float4 v0 = make_float4(acc[i][0], acc[i][1], acc[i][2], acc[i][3]);
            float4 v1 = make_float4(acc[i][4], acc[i][5], acc[i][6], acc[i][7]);
            *(float4*)&C[(size_t)r * M + colBase + tx * 8]     = v0;
            *(float4*)&C[(size_t)r * M + colBase + tx * 8 + 4] = v1;
        }
    }
}

// ---------------------------------------------------------------------------
// al_s / al_d per (node, head)
// ---------------------------------------------------------------------------
template <int OUT, int C, int H>
__global__ void k_al(const float* __restrict__ h, const float* __restrict__ as,
                     const float* __restrict__ ad, float* __restrict__ als,
                     float* __restrict__ ald) {
    constexpr int R = C / 32;
    int n = blockIdx.x, t = threadIdx.x;   // blockDim == H*32
    const float* hp = h + (size_t)n * OUT + t * R;
    float ps = 0.f, pd = 0.f;
#pragma unroll
    for (int j = 0; j < R; j++) {
        float v = hp[j];
        ps += v * as[t * R + j];
        pd += v * ad[t * R + j];
    }
#pragma unroll
    for (int o = 16; o > 0; o >>= 1) {
        ps += __shfl_down_sync(0xFFFFFFFFu, ps, o);
        pd += __shfl_down_sync(0xFFFFFFFFu, pd, o);
    }
    if ((t & 31) == 0) {
        int w = t >> 5;
        als[n * H + w] = ps;
        ald[n * H + w] = pd;
    }
}

// ---------------------------------------------------------------------------
// softmax stats per (node, head)
// ---------------------------------------------------------------------------
template <int H>
__global__ void k_stats(const float* __restrict__ als, const float* __restrict__ ald,
                        float* __restrict__ emax, float* __restrict__ dinv) {
    int idx = blockIdx.x * blockDim.x + threadIdx.x;
    if (idx >= NN * H) return;
    int n = idx / H, hh = idx - n * H;
    float ad = ald[idx];
    int s0 = g_off[n], s1 = g_off[n + 1];
    float m = -FLT_MAX;
    for (int j = s0; j < s1; j++) {
        float e = als[g_srcS[j] * H + hh] + ad;
        e = fmaxf(e, 0.2f * e);
        m = fmaxf(m, e);
    }
    float ssum = 0.f;
    for (int j = s0; j < s1; j++) {
        float e = als[g_srcS[j] * H + hh] + ad;
        e = fmaxf(e, 0.2f * e);
        ssum += __expf(e - m);
    }
    emax[idx] = m;
    dinv[idx] = 1.f / (ssum + 1e-16f);
}

// ---------------------------------------------------------------------------
// Aggregation: out[n] = lrelu_{0.01}( sum_e alpha * h[src] + bias )
// ---------------------------------------------------------------------------
template <int OUT, int H, int C>
__global__ void k_agg(const float* __restrict__ h, const float* __restrict__ als,
                      const float* __restrict__ ald, const float* __restrict__ emax,
                      const float* __restrict__ dinv, const float* __restrict__ bias,
                      float* __restrict__ out) {
    constexpr int T = (OUT < 256) ? OUT : 256;
    constexpr int R = OUT / T;
    __shared__ int   ssrc[32];
    __shared__ float salpha[32 * H];
    int n = blockIdx.x, t = threadIdx.x;
    int myhead = (t * R) / C;

    float acc[R];
#pragma unroll
    for (int j = 0; j < R; j++) acc[j] = 0.f;

    int s0 = g_off[n], s1 = g_off[n + 1];
    for (int e0 = s0; e0 < s1; e0 += 32) {
        int cs = min(32, s1 - e0);
        if (t < cs) ssrc[t] = g_srcS[e0 + t];
        __syncthreads();
        if (t < cs * H) {
            int i = t / H, hh = t - i * H;
            float e = als[ssrc[i] * H + hh] + ald[n * H + hh];
            e = fmaxf(e, 0.2f * e);
            salpha[i * H + hh] = __expf(e - emax[n * H + hh]) * dinv[n * H + hh];
        }
        __syncthreads();
        for (int i = 0; i < cs; i++) {
            float a = salpha[i * H + myhead];
            const float* hp = h + (size_t)ssrc[i] * OUT + t * R;
            if constexpr (R == 4) {
                float4 v = *(const float4*)hp;
                acc[0] += a * v.x; acc[1] += a * v.y;
                acc[2] += a * v.z; acc[3] += a * v.w;
            } else if constexpr (R == 2) {
                float2 v = *(const float2*)hp;
                acc[0] += a * v.x; acc[1] += a * v.y;
            } else {
                acc[0] += a * hp[0];
            }
        }
        __syncthreads();
    }
#pragma unroll
    for (int j = 0; j < R; j++) {
        float v = acc[j] + bias[t * R + j];
        out[(size_t)n * OUT + t * R + j] = (v > 0.f) ? v : 0.01f * v;
    }
}

// ---------------------------------------------------------------------------
// Pooling + output head
// ---------------------------------------------------------------------------
__global__ void k_zero_pool() {
    int i = blockIdx.x * blockDim.x + threadIdx.x;
    if (i < NG * 128) g_pool[i] = 0.f;
    if (i < NG) g_cnt[i] = 0;
}

__global__ void k_pool(const int* __restrict__ batch, const float* __restrict__ o3) {
    int idx = blockIdx.x * blockDim.x + threadIdx.x;
    if (idx >= NN * 128) return;
    int n = idx >> 7, c = idx & 127;
    int g = ld_b(batch, n);
    g = (g < 0) ? 0 : ((g >= NG) ? NG - 1 : g);
    atomicAdd(&g_pool[g * 128 + c], o3[(size_t)n * 128 + c]);
    if (c == 0) atomicAdd(&g_cnt[g], 1);
}

__global__ void k_final(const float* __restrict__ Wout, const float* __restrict__ bout,
                        float* __restrict__ out) {
    int g = blockIdx.x, t = threadIdx.x;  // 128 threads
    float v = g_pool[g * 128 + t] * Wout[t];
#pragma unroll
    for (int o = 16; o > 0; o >>= 1) v += __shfl_down_sync(0xFFFFFFFFu, v, o);
    __shared__ float red[4];
    if ((t & 31) == 0) red[t >> 5] = v;
    __syncthreads();
    if (t == 0) {
        float tot = red[0] + red[1] + red[2] + red[3];
        float cnt = fmaxf((float)g_cnt[g], 1.f);
        out[g] = tot / cnt + bout[0];
    }
}

// ---------------------------------------------------------------------------
// Launch: inputs mapped by SIZE SIGNATURE (robust to metadata ordering)
// ---------------------------------------------------------------------------
extern "C" void kernel_launch(void* const* d_in, const int* in_sizes, int n_in,
                              void* d_out, int out_size) {
    // Defaults: positional (setup_inputs dict order)
    int ix = 0, iei = 1, ib = 2, iW1 = 3, ia1s = 4, ia1d = 5, ib1 = 6,
        iW2 = 7, ia2s = 8, ia2d = 9, ib2 = 10, iW3 = 11, ia3s = 12,
        ia3d = 13, ib3 = 14, iWout = 15, ibout = 16;

    // Size-signature mapping
    {
        int jx = -1, jei = -1, jb = -1, jW1 = -1, jW2 = -1, jW3 = -1, jbout = -1;
        int j1024[3], n1024 = 0;
        int j512[3],  n512 = 0;
        int j128[4],  n128 = 0;
        bool clean = true;
        for (int i = 0; i < n_in; i++) {
            int s = in_sizes[i];
            if      (s == 550000) { if (jx >= 0) clean = false; jx = i; }
            else if (s == 500000) { if (jei >= 0) clean = false; jei = i; }
            else if (s == 50000)  { if (jb >= 0) clean = false; jb = i; }
            else if (s == 11264)  { if (jW1 >= 0) clean = false; jW1 = i; }
            else if (s == 524288) { if (jW2 >= 0) clean = false; jW2 = i; }
            else if (s == 65536)  { if (jW3 >= 0) clean = false; jW3 = i; }
            else if (s == 1024)   { if (n1024 < 3) j1024[n1024] = i; n1024++; }
            else if (s == 512)    { if (n512  < 3) j512[n512]   = i; n512++; }
            else if (s == 128)    { if (n128  < 4) j128[n128]   = i; n128++; }
            else if (s == 1)      { if (jbout >= 0) clean = false; jbout = i; }
            else clean = false;
        }
        if (clean && jx >= 0 && jei >= 0 && jb >= 0 && jW1 >= 0 && jW2 >= 0 &&
            jW3 >= 0 && jbout >= 0 && n1024 == 3 && n512 == 3 && n128 == 4) {
            ix = jx; iei = jei; ib = jb; iW1 = jW1; iW2 = jW2; iW3 = jW3;
            ia1s = j1024[0]; ia1d = j1024[1]; ib1 = j1024[2];
            ia2s = j512[0];  ia2d = j512[1];  ib2 = j512[2];
            ia3s = j128[0];  ia3d = j128[1];  ib3 = j128[2]; iWout = j128[3];
            ibout = jbout;
        }
    }

    const float* x    = (const float*)d_in[ix];
    const int*   ei   = (const int*)d_in[iei];
    const int*   batch= (const int*)d_in[ib];
    const float* W1   = (const float*)d_in[iW1];
    const float* a1s  = (const float*)d_in[ia1s];
    const float* a1d  = (const float*)d_in[ia1d];
    const float* b1   = (const float*)d_in[ib1];
    const float* W2   = (const float*)d_in[iW2];
    const float* a2s  = (const float*)d_in[ia2s];
    const float* a2d  = (const float*)d_in[ia2d];
    const float* b2   = (const float*)d_in[ib2];
    const float* W3   = (const float*)d_in[iW3];
    const float* a3s  = (const float*)d_in[ia3s];
    const float* a3d  = (const float*)d_in[ia3d];
    const float* b3   = (const float*)d_in[ib3];
    const float* Wout = (const float*)d_in[iWout];
    const float* bout = (const float*)d_in[ibout];
    float* out = (float*)d_out;

    float* P = nullptr; cudaGetSymbolAddress((void**)&P, g_P);
    float* Q = nullptr; cudaGetSymbolAddress((void**)&Q, g_Q);
    float* als = nullptr; cudaGetSymbolAddress((void**)&als, g_als);
    float* ald = nullptr; cudaGetSymbolAddress((void**)&ald, g_ald);
    float* emax = nullptr; cudaGetSymbolAddress((void**)&emax, g_emax);
    float* dinv = nullptr; cudaGetSymbolAddress((void**)&dinv, g_dinv);

    // dtype detection + CSR build
    k_detect<<<1, 32>>>(ei, batch);
    k_zero_deg<<<(NN + 255) / 256, 256>>>();
    k_count<<<(ET + 255) / 256, 256>>>(ei);
    k_scan_simple<<<1, 256>>>();
    k_init_cur<<<(NN + 255) / 256, 256>>>();
    k_scatter<<<(ET + 255) / 256, 256>>>(ei);

    // ---- Layer 1: IN=11, H=8, C=128, OUT=1024 ----   h1=P, o1=Q
    {
        dim3 grid(NN, 4);
        k_gemm1<<<grid, 256>>>(x, W1, P);
        k_al<1024, 128, 8><<<NN, 256>>>(P, a1s, a1d, als, ald);
        k_stats<8><<<(NN * 8 + 255) / 256, 256>>>(als, ald, emax, dinv);
        k_agg<1024, 8, 128><<<NN, 256>>>(P, als, ald, emax, dinv, b1, Q);
    }

    // ---- Layer 2: IN=1024, H=8, C=64, OUT=512 ----   h2=P, o2=Q
    {
        dim3 grid((NN + 127) / 128, 4);
        k_sgemm<<<grid, 256>>>(Q, W2, P, NN, 1024, 512);
        k_al<512, 64, 8><<<NN, 256>>>(P, a2s, a2d, als, ald);
        k_stats<8><<<(NN * 8 + 255) / 256, 256>>>(als, ald, emax, dinv);
        k_agg<512, 8, 64><<<NN, 256>>>(P, als, ald, emax, dinv, b2, Q);
    }

    // ---- Layer 3: IN=512, H=4, C=32, OUT=128 ----    h3=P, o3=Q
    {
        dim3 grid((NN + 127) / 128, 1);
        k_sgemm<<<grid, 256>>>(Q, W3, P, NN, 512, 128);
        k_al<128, 32, 4><<<NN, 128>>>(P, a3s, a3d, als, ald);
        k_stats<4><<<(NN * 4 + 255) / 256, 256>>>(als, ald, emax, dinv);
        k_agg<128, 4, 32><<<NN, 128>>>(P, als, ald, emax, dinv, b3, Q);
    }

    // ---- Pool + head ----
    k_zero_pool<<<(NG * 128 + 255) / 256, 256>>>();
    k_pool<<<(NN * 128 + 255) / 256, 256>>>(batch, Q);
    k_final<<<NG, 128>>>(Wout, bout, out);
}

// round 5
// speedup vs baseline: 1.5685x; 1.5685x over previous
#include <cuda_runtime.h>
#include <cuda_bf16.h>
#include <float.h>
#include <stdint.h>

#define NN   50000
#define EE   250000
#define ET   300000
#define NG   64

// ---------------------------------------------------------------------------
// Device scratch
// ---------------------------------------------------------------------------
__device__ __align__(16) float g_P[(size_t)NN * 1024];   // h2 / h3
__device__ __align__(16) float g_Q[(size_t)NN * 1024];   // o1 / o2 / o3
__device__ __align__(16) float g_z[(size_t)NN * 88];     // layer-1 aggregated x

__device__ float g_als[NN * 8];
__device__ float g_ald[NN * 8];
__device__ float g_emax[NN * 8];
__device__ float g_dinv[NN * 8];
__device__ float g_ws[11 * 8];
__device__ float g_wd[11 * 8];

__device__ int   g_srcS[ET];
__device__ int   g_deg[NN];
__device__ int   g_off[NN + 1];
__device__ int   g_cur[NN];

__device__ int g_ei64;
__device__ int g_b64;

__device__ __forceinline__ int clampN(int v) {
    return (v < 0) ? 0 : ((v >= NN) ? NN - 1 : v);
}

// ---------------------------------------------------------------------------
// Dtype detection (int32 vs int64 index inputs)
// ---------------------------------------------------------------------------
__global__ void k_detect(const int* __restrict__ ei, const int* __restrict__ batch) {
    if (threadIdx.x != 0) return;
    int all0 = 1;
    for (int i = 1; i < 1024; i += 2)
        if (ei[i] != 0) { all0 = 0; break; }
    g_ei64 = all0;
    all0 = 1;
    for (int i = NN - 1023; i < NN; i += 2)
        if (batch[i] != 0) { all0 = 0; break; }
    g_b64 = all0;
}

__device__ __forceinline__ int ld_ei(const int* __restrict__ ei, int i) {
    return g_ei64 ? ei[2 * i] : ei[i];
}
__device__ __forceinline__ int ld_b(const int* __restrict__ b, int i) {
    return g_b64 ? b[2 * i] : b[i];
}

// ---------------------------------------------------------------------------
// CSR build
// ---------------------------------------------------------------------------
__global__ void k_zero_deg() {
    int i = blockIdx.x * blockDim.x + threadIdx.x;
    if (i < NN) g_deg[i] = 0;
}

__global__ void k_count(const int* __restrict__ ei) {
    int e = blockIdx.x * blockDim.x + threadIdx.x;
    if (e >= ET) return;
    int dst = (e < EE) ? clampN(ld_ei(ei, EE + e)) : (e - EE);
    atomicAdd(&g_deg[dst], 1);
}

__global__ void k_scan_simple() {   // 1 block, 1024 threads
    __shared__ int strip[1024];
    int tid = threadIdx.x;
    const int SZ = (NN + 1023) / 1024;
    int lo = tid * SZ; if (lo > NN) lo = NN;
    int hi = lo + SZ;  if (hi > NN) hi = NN;
    int s = 0;
    for (int i = lo; i < hi; i++) s += g_deg[i];
    strip[tid] = s;
    __syncthreads();
    if (tid == 0) {
        int run = 0;
        for (int i = 0; i < 1024; i++) { int t = strip[i]; strip[i] = run; run += t; }
        g_off[NN] = run;
    }
    __syncthreads();
    int run = strip[tid];
    for (int i = lo; i < hi; i++) { g_off[i] = run; run += g_deg[i]; }
}

__global__ void k_init_cur() {
    int i = blockIdx.x * blockDim.x + threadIdx.x;
    if (i < NN) g_cur[i] = g_off[i];
}

__global__ void k_scatter(const int* __restrict__ ei) {
    int e = blockIdx.x * blockDim.x + threadIdx.x;
    if (e >= ET) return;
    int src, dst;
    if (e < EE) { src = clampN(ld_ei(ei, e)); dst = clampN(ld_ei(ei, EE + e)); }
    else        { src = e - EE;               dst = e - EE; }
    int pos = atomicAdd(&g_cur[dst], 1);
    if (pos >= 0 && pos < ET) g_srcS[pos] = src;
}

// ---------------------------------------------------------------------------
// Layer-1 algebraic path
// ws[k][h] = sum_c W1[k][h*128+c] * a1s[h][c]   (and wd with a1d)
// ---------------------------------------------------------------------------
__global__ void k_wsd(const float* __restrict__ W1, const float* __restrict__ a1s,
                      const float* __restrict__ a1d) {
    int t = threadIdx.x;
    if (t >= 88) return;
    int k = t / 8, h = t % 8;
    float ss = 0.f, sd = 0.f;
    const float* wrow = W1 + k * 1024 + h * 128;
    const float* asr  = a1s + h * 128;
    const float* adr  = a1d + h * 128;
    for (int c = 0; c < 128; c++) {
        float w = wrow[c];
        ss += w * asr[c];
        sd += w * adr[c];
    }
    g_ws[k * 8 + h] = ss;
    g_wd[k * 8 + h] = sd;
}

// al_s[n][h] = x[n] . ws[:,h]
__global__ void k_alx(const float* __restrict__ x) {
    __shared__ float ws[88], wd[88];
    int t = threadIdx.x;
    if (t < 88) { ws[t] = g_ws[t]; wd[t] = g_wd[t]; }
    __syncthreads();
    int n = blockIdx.x * blockDim.x + t;
    if (n >= NN) return;
    float xv[11];
#pragma unroll
    for (int k = 0; k < 11; k++) xv[k] = x[n * 11 + k];
#pragma unroll
    for (int h = 0; h < 8; h++) {
        float ps = 0.f, pd = 0.f;
#pragma unroll
        for (int k = 0; k < 11; k++) {
            ps += xv[k] * ws[k * 8 + h];
            pd += xv[k] * wd[k * 8 + h];
        }
        g_als[n * 8 + h] = ps;
        g_ald[n * 8 + h] = pd;
    }
}

// softmax stats per (node, head)
template <int H>
__global__ void k_stats(const float* __restrict__ als, const float* __restrict__ ald,
                        float* __restrict__ emax, float* __restrict__ dinv) {
    int idx = blockIdx.x * blockDim.x + threadIdx.x;
    if (idx >= NN * H) return;
    int n = idx / H, hh = idx - n * H;
    float ad = ald[idx];
    int s0 = g_off[n], s1 = g_off[n + 1];
    float m = -FLT_MAX;
    for (int j = s0; j < s1; j++) {
        float e = als[g_srcS[j] * H + hh] + ad;
        e = fmaxf(e, 0.2f * e);
        m = fmaxf(m, e);
    }
    float ssum = 0.f;
    for (int j = s0; j < s1; j++) {
        float e = als[g_srcS[j] * H + hh] + ad;
        e = fmaxf(e, 0.2f * e);
        ssum += __expf(e - m);
    }
    emax[idx] = m;
    dinv[idx] = 1.f / (ssum + 1e-16f);
}

// z[n][h][k] = sum_e alpha_eh * x[src_e][k]   (thread per node)
__global__ void k_aggx(const float* __restrict__ x) {
    int n = blockIdx.x * blockDim.x + threadIdx.x;
    if (n >= NN) return;
    float z[88];
#pragma unroll
    for (int i = 0; i < 88; i++) z[i] = 0.f;
    float ad[8], em[8], dv[8];
#pragma unroll
    for (int h = 0; h < 8; h++) {
        ad[h] = g_ald[n * 8 + h];
        em[h] = g_emax[n * 8 + h];
        dv[h] = g_dinv[n * 8 + h];
    }
    int s0 = g_off[n], s1 = g_off[n + 1];
    for (int j = s0; j < s1; j++) {
        int s = g_srcS[j];
        float xs_[11];
#pragma unroll
        for (int k = 0; k < 11; k++) xs_[k] = x[s * 11 + k];
#pragma unroll
        for (int h = 0; h < 8; h++) {
            float e = g_als[s * 8 + h] + ad[h];
            e = fmaxf(e, 0.2f * e);
            float a = __expf(e - em[h]) * dv[h];
#pragma unroll
            for (int k = 0; k < 11; k++) z[h * 11 + k] += a * xs_[k];
        }
    }
#pragma unroll
    for (int i = 0; i < 88; i++) g_z[(size_t)n * 88 + i] = z[i];
}

// o1[n][h*128+c] = lrelu( z[n][h] . W1[:, h*128+c] + b1 )
__global__ __launch_bounds__(256) void k_proj(const float* __restrict__ W1,
                                              const float* __restrict__ b1,
                                              float* __restrict__ o1) {
    __shared__ float Wh[11][128];
    __shared__ float zt[64][11];
    int n0 = blockIdx.x * 64;
    int h = blockIdx.y;
    int t = threadIdx.x;
    // load W1 head slice
    for (int i = t; i < 11 * 128; i += 256) {
        int k = i >> 7, c = i & 127;
        Wh[k][c] = W1[k * 1024 + h * 128 + c];
    }
    // load z tile
    for (int i = t; i < 64 * 11; i += 256) {
        int r = i / 11, k = i - r * 11;
        int n = n0 + r;
        zt[r][k] = (n < NN) ? g_z[(size_t)n * 88 + h * 11 + k] : 0.f;
    }
    __syncthreads();
    int c = t & 127;
    int r0 = (t >> 7) * 32;
    float bias = b1[h * 128 + c];
#pragma unroll 4
    for (int i = 0; i < 32; i++) {
        int r = r0 + i;
        int n = n0 + r;
        if (n >= NN) break;
        float acc = bias;
#pragma unroll
        for (int k = 0; k < 11; k++) acc += zt[r][k] * Wh[k][c];
        o1[(size_t)n * 1024 + h * 128 + c] = (acc > 0.f) ? acc : 0.01f * acc;
    }
}

// ---------------------------------------------------------------------------
// TF32 tensor-core GEMM with 3xTF32 error compensation.
// C(Nrows x M) = A(Nrows x K) @ B(K x M). BM=128, BN=128, BK=32.
// ---------------------------------------------------------------------------
__device__ __forceinline__ void mma_tf32(float* c, const uint32_t* a, const uint32_t* b) {
    asm volatile(
        "mma.sync.aligned.m16n8k8.row.col.f32.tf32.tf32.f32 "
        "{%0,%1,%2,%3}, {%4,%5,%6,%7}, {%8,%9}, {%0,%1,%2,%3};"
        : "+f"(c[0]), "+f"(c[1]), "+f"(c[2]), "+f"(c[3])
        : "r"(a[0]), "r"(a[1]), "r"(a[2]), "r"(a[3]), "r"(b[0]), "r"(b[1]));
}

__device__ __forceinline__ void split_tf32(float v, uint32_t& hi, uint32_t& lo) {
    uint32_t h;
    asm("cvt.rna.tf32.f32 %0, %1;" : "=r"(h) : "f"(v));
    float rem = v - __uint_as_float(h);
    asm("cvt.rna.tf32.f32 %0, %1;" : "=r"(lo) : "f"(rem));
    hi = h;
}

__global__ __launch_bounds__(256) void k_sgemm_tc(const float* __restrict__ A,
                                                  const float* __restrict__ B,
                                                  float* __restrict__ C,
                                                  int Nrows, int K, int M) {
    __shared__ float As[32][132];   // [k][m]
    __shared__ float Bs[32][132];   // [k][n]
    int tid = threadIdx.x;
    int lane = tid & 31, warp = tid >> 5;
    int g = lane >> 2, tg = lane & 3;
    int rowBase = blockIdx.x * 128;
    int colBase = blockIdx.y * 128;
    int warpM = (warp & 1) * 64;
    int warpN = (warp >> 1) * 32;

    float c[4][4][4];
#pragma unroll
    for (int mt = 0; mt < 4; mt++)
#pragma unroll
        for (int nt = 0; nt < 4; nt++)
#pragma unroll
            for (int i = 0; i < 4; i++) c[mt][nt][i] = 0.f;

    for (int kt = 0; kt < K; kt += 32) {
        // load A tile (transposed into As[k][m])
        {
            int row = tid >> 1;
            int gr = rowBase + row;
            bool v = gr < Nrows;
            const float* ap = A + (size_t)gr * K + kt;
#pragma unroll
            for (int i = 0; i < 4; i++) {
                int k4 = ((tid & 1) + 2 * i) * 4;
                float4 av = v ? *(const float4*)(ap + k4) : make_float4(0, 0, 0, 0);
                As[k4 + 0][row] = av.x;
                As[k4 + 1][row] = av.y;
                As[k4 + 2][row] = av.z;
                As[k4 + 3][row] = av.w;
            }
        }
        // load B tile
        {
            int row = tid >> 3;
            const float* bp = B + (size_t)(kt + row) * M + colBase;
#pragma unroll
            for (int i = 0; i < 4; i++) {
                int col = ((tid & 7) + 8 * i) * 4;
                float4 bv = *(const float4*)(bp + col);
                *(float4*)&Bs[row][col] = bv;
            }
        }
        __syncthreads();

#pragma unroll
        for (int kk = 0; kk < 32; kk += 8) {
            uint32_t ah[4][4], al[4][4], bh[4][2], bl[4][2];
#pragma unroll
            for (int mt = 0; mt < 4; mt++) {
                int r0 = warpM + mt * 16 + g;
                float a0 = As[kk + tg][r0];
                float a1 = As[kk + tg][r0 + 8];
                float a2 = As[kk + tg + 4][r0];
                float a3 = As[kk + tg + 4][r0 + 8];
                split_tf32(a0, ah[mt][0], al[mt][0]);
                split_tf32(a1, ah[mt][1], al[mt][1]);
                split_tf32(a2, ah[mt][2], al[mt][2]);
                split_tf32(a3, ah[mt][3], al[mt][3]);
            }
#pragma unroll
            for (int nt = 0; nt < 4; nt++) {
                int c0i = warpN + nt * 8 + g;
                float b0 = Bs[kk + tg][c0i];
                float b1 = Bs[kk + tg + 4][c0i];
                split_tf32(b0, bh[nt][0], bl[nt][0]);
                split_tf32(b1, bh[nt][1], bl[nt][1]);
            }
#pragma unroll
            for (int mt = 0; mt < 4; mt++)
#pragma unroll
                for (int nt = 0; nt < 4; nt++) {
                    mma_tf32(c[mt][nt], ah[mt], bh[nt]);
                    mma_tf32(c[mt][nt], ah[mt], bl[nt]);
                    mma_tf32(c[mt][nt], al[mt], bh[nt]);
                }
        }
        __syncthreads();
    }

#pragma unroll
    for (int mt = 0; mt < 4; mt++) {
#pragma unroll
        for (int nt = 0; nt < 4; nt++) {
            int r = rowBase + warpM + mt * 16 + g;
            int cc = colBase + warpN + nt * 8 + tg * 2;
            if (r < Nrows)
                *(float2*)&C[(size_t)r * M + cc] = make_float2(c[mt][nt][0], c[mt][nt][1]);
            if (r + 8 < Nrows)
                *(float2*)&C[(size_t)(r + 8) * M + cc] = make_float2(c[mt][nt][2], c[mt][nt][3]);
        }
    }
}

// ---------------------------------------------------------------------------
// al_s / al_d per (node, head) from dense h
// ---------------------------------------------------------------------------
template <int OUT, int C, int H>
__global__ void k_al(const float* __restrict__ h, const float* __restrict__ as,
                     const float* __restrict__ ad, float* __restrict__ als,
                     float* __restrict__ ald) {
    constexpr int R = C / 32;
    int n = blockIdx.x, t = threadIdx.x;   // blockDim == H*32
    const float* hp = h + (size_t)n * OUT + t * R;
    float ps = 0.f, pd = 0.f;
#pragma unroll
    for (int j = 0; j < R; j++) {
        float v = hp[j];
        ps += v * as[t * R + j];
        pd += v * ad[t * R + j];
    }
#pragma unroll
    for (int o = 16; o > 0; o >>= 1) {
        ps += __shfl_down_sync(0xFFFFFFFFu, ps, o);
        pd += __shfl_down_sync(0xFFFFFFFFu, pd, o);
    }
    if ((t & 31) == 0) {
        int w = t >> 5;
        als[n * H + w] = ps;
        ald[n * H + w] = pd;
    }
}

// ---------------------------------------------------------------------------
// Aggregation: out[n] = lrelu_{0.01}( sum_e alpha * h[src] + bias )
// ---------------------------------------------------------------------------
template <int OUT, int H, int C>
__global__ void k_agg(const float* __restrict__ h, const float* __restrict__ als,
                      const float* __restrict__ ald, const float* __restrict__ emax,
                      const float* __restrict__ dinv, const float* __restrict__ bias,
                      float* __restrict__ out) {
    constexpr int T = (OUT < 256) ? OUT : 256;
    constexpr int R = OUT / T;
    __shared__ int   ssrc[32];
    __shared__ float salpha[32 * H];
    int n = blockIdx.x, t = threadIdx.x;
    int myhead = (t * R) / C;

    float acc[R];
#pragma unroll
    for (int j = 0; j < R; j++) acc[j] = 0.f;

    int s0 = g_off[n], s1 = g_off[n + 1];
    for (int e0 = s0; e0 < s1; e0 += 32) {
        int cs = min(32, s1 - e0);
        if (t < cs) ssrc[t] = g_srcS[e0 + t];
        __syncthreads();
        if (t < cs * H) {
            int i = t / H, hh = t - i * H;
            float e = als[ssrc[i] * H + hh] + ald[n * H + hh];
            e = fmaxf(e, 0.2f * e);
            salpha[i * H + hh] = __expf(e - emax[n * H + hh]) * dinv[n * H + hh];
        }
        __syncthreads();
        for (int i = 0; i < cs; i++) {
            float a = salpha[i * H + myhead];
            const float* hp = h + (size_t)ssrc[i] * OUT + t * R;
            if constexpr (R == 2) {
                float2 v = *(const float2*)hp;
                acc[0] += a * v.x; acc[1] += a * v.y;
            } else {
                acc[0] += a * hp[0];
            }
        }
        __syncthreads();
    }
#pragma unroll
    for (int j = 0; j < R; j++) {
        float v = acc[j] + bias[t * R + j];
        out[(size_t)n * OUT + t * R + j] = (v > 0.f) ? v : 0.01f * v;
    }
}

// ---------------------------------------------------------------------------
// Pooling + head: batch is sorted -> per-graph contiguous node ranges.
// ---------------------------------------------------------------------------
__device__ __forceinline__ int lower_bound_b(const int* __restrict__ b, int val) {
    int lo = 0, hi = NN;
    while (lo < hi) {
        int mid = (lo + hi) >> 1;
        if (ld_b(b, mid) < val) lo = mid + 1; else hi = mid;
    }
    return lo;
}

__global__ void k_poolseg(const int* __restrict__ batch, const float* __restrict__ o3,
                          const float* __restrict__ Wout, const float* __restrict__ bout,
                          float* __restrict__ out) {
    int gph = blockIdx.x, t = threadIdx.x;   // 128 threads
    int lo = lower_bound_b(batch, gph);
    int hi = lower_bound_b(batch, gph + 1);
    float s = 0.f;
    for (int n = lo; n < hi; n++) s += o3[(size_t)n * 128 + t];
    float cnt = fmaxf((float)(hi - lo), 1.f);
    float v = (s / cnt) * Wout[t];
#pragma unroll
    for (int o = 16; o > 0; o >>= 1) v += __shfl_down_sync(0xFFFFFFFFu, v, o);
    __shared__ float red[4];
    if ((t & 31) == 0) red[t >> 5] = v;
    __syncthreads();
    if (t == 0) out[gph] = red[0] + red[1] + red[2] + red[3] + bout[0];
}

// ---------------------------------------------------------------------------
// Launch
// ---------------------------------------------------------------------------
extern "C" void kernel_launch(void* const* d_in, const int* in_sizes, int n_in,
                              void* d_out, int out_size) {
    int ix = 0, iei = 1, ib = 2, iW1 = 3, ia1s = 4, ia1d = 5, ib1 = 6,
        iW2 = 7, ia2s = 8, ia2d = 9, ib2 = 10, iW3 = 11, ia3s = 12,
        ia3d = 13, ib3 = 14, iWout = 15, ibout = 16;
    {
        int jx = -1, jei = -1, jb = -1, jW1 = -1, jW2 = -1, jW3 = -1, jbout = -1;
        int j1024[3], n1024 = 0;
        int j512[3],  n512 = 0;
        int j128[4],  n128 = 0;
        bool clean = true;
        for (int i = 0; i < n_in; i++) {
            int s = in_sizes[i];
            if      (s == 550000) { if (jx >= 0) clean = false; jx = i; }
            else if (s == 500000) { if (jei >= 0) clean = false; jei = i; }
            else if (s == 50000)  { if (jb >= 0) clean = false; jb = i; }
            else if (s == 11264)  { if (jW1 >= 0) clean = false; jW1 = i; }
            else if (s == 524288) { if (jW2 >= 0) clean = false; jW2 = i; }
            else if (s == 65536)  { if (jW3 >= 0) clean = false; jW3 = i; }
            else if (s == 1024)   { if (n1024 < 3) j1024[n1024] = i; n1024++; }
            else if (s == 512)    { if (n512  < 3) j512[n512]   = i; n512++; }
            else if (s == 128)    { if (n128  < 4) j128[n128]   = i; n128++; }
            else if (s == 1)      { if (jbout >= 0) clean = false; jbout = i; }
            else clean = false;
        }
        if (clean && jx >= 0 && jei >= 0 && jb >= 0 && jW1 >= 0 && jW2 >= 0 &&
            jW3 >= 0 && jbout >= 0 && n1024 == 3 && n512 == 3 && n128 == 4) {
            ix = jx; iei = jei; ib = jb; iW1 = jW1; iW2 = jW2; iW3 = jW3;
            ia1s = j1024[0]; ia1d = j1024[1]; ib1 = j1024[2];
            ia2s = j512[0];  ia2d = j512[1];  ib2 = j512[2];
            ia3s = j128[0];  ia3d = j128[1];  ib3 = j128[2]; iWout = j128[3];
            ibout = jbout;
        }
    }

    const float* x    = (const float*)d_in[ix];
    const int*   ei   = (const int*)d_in[iei];
    const int*   batch= (const int*)d_in[ib];
    const float* W1   = (const float*)d_in[iW1];
    const float* a1s  = (const float*)d_in[ia1s];
    const float* a1d  = (const float*)d_in[ia1d];
    const float* b1   = (const float*)d_in[ib1];
    const float* W2   = (const float*)d_in[iW2];
    const float* a2s  = (const float*)d_in[ia2s];
    const float* a2d  = (const float*)d_in[ia2d];
    const float* b2   = (const float*)d_in[ib2];
    const float* W3   = (const float*)d_in[iW3];
    const float* a3s  = (const float*)d_in[ia3s];
    const float* a3d  = (const float*)d_in[ia3d];
    const float* b3   = (const float*)d_in[ib3];
    const float* Wout = (const float*)d_in[iWout];
    const float* bout = (const float*)d_in[ibout];
    float* out = (float*)d_out;

    float* P = nullptr;   cudaGetSymbolAddress((void**)&P, g_P);
    float* Q = nullptr;   cudaGetSymbolAddress((void**)&Q, g_Q);
    float* als = nullptr; cudaGetSymbolAddress((void**)&als, g_als);
    float* ald = nullptr; cudaGetSymbolAddress((void**)&ald, g_ald);
    float* emax = nullptr; cudaGetSymbolAddress((void**)&emax, g_emax);
    float* dinv = nullptr; cudaGetSymbolAddress((void**)&dinv, g_dinv);

    // dtype detection + CSR build
    k_detect<<<1, 32>>>(ei, batch);
    k_zero_deg<<<(NN + 255) / 256, 256>>>();
    k_count<<<(ET + 255) / 256, 256>>>(ei);
    k_scan_simple<<<1, 1024>>>();
    k_init_cur<<<(NN + 255) / 256, 256>>>();
    k_scatter<<<(ET + 255) / 256, 256>>>(ei);

    // ---- Layer 1 (algebraic): o1 = Q ----
    k_wsd<<<1, 128>>>(W1, a1s, a1d);
    k_alx<<<(NN + 255) / 256, 256>>>(x);
    k_stats<8><<<(NN * 8 + 255) / 256, 256>>>(als, ald, emax, dinv);
    k_aggx<<<(NN + 127) / 128, 128>>>(x);
    {
        dim3 grid((NN + 63) / 64, 8);
        k_proj<<<grid, 256>>>(W1, b1, Q);
    }

    // ---- Layer 2: h2 = Q @ W2 (tf32 TC), agg -> Q ----
    {
        dim3 grid((NN + 127) / 128, 4);
        k_sgemm_tc<<<grid, 256>>>(Q, W2, P, NN, 1024, 512);
        k_al<512, 64, 8><<<NN, 256>>>(P, a2s, a2d, als, ald);
        k_stats<8><<<(NN * 8 + 255) / 256, 256>>>(als, ald, emax, dinv);
        k_agg<512, 8, 64><<<NN, 256>>>(P, als, ald, emax, dinv, b2, Q);
    }

    // ---- Layer 3: h3 = Q @ W3 (tf32 TC), agg -> Q ----
    {
        dim3 grid((NN + 127) / 128, 1);
        k_sgemm_tc<<<grid, 256>>>(Q, W3, P, NN, 512, 128);
        k_al<128, 32, 4><<<NN, 128>>>(P, a3s, a3d, als, ald);
        k_stats<4><<<(NN * 4 + 255) / 256, 256>>>(als, ald, emax, dinv);
        k_agg<128, 4, 32><<<NN, 128>>>(P, als, ald, emax, dinv, b3, Q);
    }

    // ---- Pool + head (deterministic, no atomics) ----
    k_poolseg<<<NG, 128>>>(batch, Q, Wout, bout, out);
}